// round 2
// baseline (speedup 1.0000x reference)
#include <cuda_runtime.h>

// Problem constants
#define Bv   8
#define SQv  2048
#define SKv  2048
#define Dv   512
#define Hv   8
#define QPv  512
#define VPv  4096
#define DQv  64     // QP / H
#define DVv  512    // VP / H

// GEMM tiling
#define BM 128
#define BN 128
#define BKK 8
#define TM 8
#define TN 8
#define NTHREADS 256

// Scratch (static device allocations — allowed; runtime alloc is not)
__device__ float g_q[(size_t)Bv * SQv * QPv];            // 33.5 MB
__device__ float g_k[(size_t)Bv * SKv * QPv];            // 33.5 MB
__device__ float g_v[(size_t)Bv * SKv * VPv];            // 268 MB
__device__ float g_S[(size_t)Bv * Hv * SQv * SKv];       // 1.07 GB
__device__ float g_O[(size_t)Hv * Bv * SQv * DVv];       // 268 MB  layout [h][b][s][d]

// ---------------------------------------------------------------------------
// Core tile GEMM: C[BMxBN] += A[BMxK] * B[KxBN]   (A,B,C row-major w/ strides)
// 256 threads, each computes an 8x8 microtile. All dims assumed multiples of
// tile sizes (true for this problem: 16384/2048 x 512/2048/4096, K % 8 == 0).
// ---------------------------------------------------------------------------
__device__ __forceinline__ void gemm_tile_nn(
    const float* __restrict__ A, int lda,
    const float* __restrict__ Bm, int ldb,
    float* __restrict__ C, int ldc,
    const float* __restrict__ bias,
    int K)
{
    __shared__ float As[BKK][BM];
    __shared__ float Bs[BKK][BN];

    const int tid  = threadIdx.x;
    const int m0   = blockIdx.y * BM;
    const int n0   = blockIdx.x * BN;
    const int tr   = tid >> 4;          // 0..15
    const int tc   = tid & 15;          // 0..15
    const int arow = tid >> 1;          // 0..127
    const int acol = (tid & 1) * 4;     // 0 or 4
    const int brow = tid >> 5;          // 0..7
    const int bcol = (tid & 31) * 4;    // 0..124

    float acc[TM][TN];
    #pragma unroll
    for (int i = 0; i < TM; ++i)
        #pragma unroll
        for (int j = 0; j < TN; ++j) acc[i][j] = 0.f;

    for (int k0 = 0; k0 < K; k0 += BKK) {
        float4 av = *(const float4*)&A[(long long)(m0 + arow) * lda + k0 + acol];
        As[acol + 0][arow] = av.x;
        As[acol + 1][arow] = av.y;
        As[acol + 2][arow] = av.z;
        As[acol + 3][arow] = av.w;
        float4 bv = *(const float4*)&Bm[(long long)(k0 + brow) * ldb + n0 + bcol];
        *(float4*)&Bs[brow][bcol] = bv;
        __syncthreads();

        #pragma unroll
        for (int k = 0; k < BKK; ++k) {
            float a[TM], b[TN];
            *(float4*)&a[0] = *(const float4*)&As[k][tr * TM];
            *(float4*)&a[4] = *(const float4*)&As[k][tr * TM + 4];
            *(float4*)&b[0] = *(const float4*)&Bs[k][tc * TN];
            *(float4*)&b[4] = *(const float4*)&Bs[k][tc * TN + 4];
            #pragma unroll
            for (int i = 0; i < TM; ++i)
                #pragma unroll
                for (int j = 0; j < TN; ++j)
                    acc[i][j] = fmaf(a[i], b[j], acc[i][j]);
        }
        __syncthreads();
    }

    #pragma unroll
    for (int i = 0; i < TM; ++i) {
        long long m = m0 + tr * TM + i;
        #pragma unroll
        for (int j = 0; j < TN; j += 4) {
            int n = n0 + tc * TN + j;
            float4 o;
            o.x = acc[i][j + 0] + (bias ? bias[n + 0] : 0.f);
            o.y = acc[i][j + 1] + (bias ? bias[n + 1] : 0.f);
            o.z = acc[i][j + 2] + (bias ? bias[n + 2] : 0.f);
            o.w = acc[i][j + 3] + (bias ? bias[n + 3] : 0.f);
            *(float4*)&C[m * ldc + n] = o;
        }
    }
}

// NT variant: C = A * B^T, with B stored N x K row-major (stride ldb)
__device__ __forceinline__ void gemm_tile_nt(
    const float* __restrict__ A, int lda,
    const float* __restrict__ Bt, int ldb,
    float* __restrict__ C, int ldc,
    int K)
{
    __shared__ float As[BKK][BM];
    __shared__ float Bs[BKK][BN];

    const int tid  = threadIdx.x;
    const int m0   = blockIdx.y * BM;
    const int n0   = blockIdx.x * BN;
    const int tr   = tid >> 4;
    const int tc   = tid & 15;
    const int arow = tid >> 1;          // 0..127
    const int acol = (tid & 1) * 4;     // 0 or 4

    float acc[TM][TN];
    #pragma unroll
    for (int i = 0; i < TM; ++i)
        #pragma unroll
        for (int j = 0; j < TN; ++j) acc[i][j] = 0.f;

    for (int k0 = 0; k0 < K; k0 += BKK) {
        float4 av = *(const float4*)&A[(long long)(m0 + arow) * lda + k0 + acol];
        As[acol + 0][arow] = av.x;
        As[acol + 1][arow] = av.y;
        As[acol + 2][arow] = av.z;
        As[acol + 3][arow] = av.w;
        float4 bv = *(const float4*)&Bt[(long long)(n0 + arow) * ldb + k0 + acol];
        Bs[acol + 0][arow] = bv.x;
        Bs[acol + 1][arow] = bv.y;
        Bs[acol + 2][arow] = bv.z;
        Bs[acol + 3][arow] = bv.w;
        __syncthreads();

        #pragma unroll
        for (int k = 0; k < BKK; ++k) {
            float a[TM], b[TN];
            *(float4*)&a[0] = *(const float4*)&As[k][tr * TM];
            *(float4*)&a[4] = *(const float4*)&As[k][tr * TM + 4];
            *(float4*)&b[0] = *(const float4*)&Bs[k][tc * TN];
            *(float4*)&b[4] = *(const float4*)&Bs[k][tc * TN + 4];
            #pragma unroll
            for (int i = 0; i < TM; ++i)
                #pragma unroll
                for (int j = 0; j < TN; ++j)
                    acc[i][j] = fmaf(a[i], b[j], acc[i][j]);
        }
        __syncthreads();
    }

    #pragma unroll
    for (int i = 0; i < TM; ++i) {
        long long m = m0 + tr * TM + i;
        #pragma unroll
        for (int j = 0; j < TN; j += 4) {
            int n = n0 + tc * TN + j;
            *(float4*)&C[m * ldc + n] = *(float4*)&acc[i][j];
        }
    }
}

// ---------------------------------------------------------------------------
// Kernels
// ---------------------------------------------------------------------------

// q = q_in @ W_q  (16384 x 512 @ 512 x 512)
__global__ void k_proj_q(const float* __restrict__ X, const float* __restrict__ W) {
    gemm_tile_nn(X, Dv, W, QPv, g_q, QPv, nullptr, Dv);
}
// k = k_in @ W_k
__global__ void k_proj_k(const float* __restrict__ X, const float* __restrict__ W) {
    gemm_tile_nn(X, Dv, W, QPv, g_k, QPv, nullptr, Dv);
}
// v = v_in @ W_v  (16384 x 4096)
__global__ void k_proj_v(const float* __restrict__ X, const float* __restrict__ W) {
    gemm_tile_nn(X, Dv, W, VPv, g_v, VPv, nullptr, Dv);
}

// S[b,h] = Q_h @ K_h^T   (2048 x 2048, K = 64), grid.z = b*H + h
__global__ void k_qk() {
    int p = blockIdx.z;
    int b = p >> 3, h = p & 7;
    const float* Qh = g_q + (long long)b * SQv * QPv + h * DQv;
    const float* Kh = g_k + (long long)b * SKv * QPv + h * DQv;
    float* Sp = g_S + (long long)p * SQv * SKv;
    gemm_tile_nt(Qh, QPv, Kh, QPv, Sp, SKv, DQv);
}

// In-place masked softmax over rows of S. grid = (SQ, B*H), 256 threads.
__global__ void k_softmax() {
    const int p = blockIdx.y;
    const int b = p >> 3;
    const int i = blockIdx.x;
    float* row = g_S + ((long long)p * SQv + i) * SKv;
    const int tid = threadIdx.x;

    // mask pointer comes from a device-visible copy set up by kernel args;
    // we read it via the global pointer stored below.
    extern __shared__ float sred[];   // 256 floats
    const int* mrow = ((const int* const*)0 == 0) ? nullptr : nullptr; // placeholder (unused)
    (void)mrow;

    // mask is passed through constant kernel parameter instead:
    // (see k_softmax_m below)
    (void)row; (void)b; (void)tid; (void)sred;
}

// Real softmax kernel (takes mask pointer as parameter)
__global__ void k_softmax_m(const int* __restrict__ mask) {
    const int p = blockIdx.y;          // b*H + h
    const int b = p >> 3;
    const int i = blockIdx.x;
    float* __restrict__ row = g_S + ((long long)p * SQv + i) * SKv;
    const int* __restrict__ mrow = mask + ((long long)b * SQv + i) * SKv;
    const int tid = threadIdx.x;       // 256 threads, 8 elems each

    __shared__ float red[256];

    float v[8];
    float mx = -3.402823466e+38f;
    #pragma unroll
    for (int t = 0; t < 8; ++t) {
        int j = tid + t * 256;
        float x = row[j];
        if (mrow[j] == 0) x = -1e9f;
        x *= 0.125f;                   // / sqrt(512/8) = /8
        v[t] = x;
        mx = fmaxf(mx, x);
    }
    red[tid] = mx;
    __syncthreads();
    for (int s = 128; s > 0; s >>= 1) {
        if (tid < s) red[tid] = fmaxf(red[tid], red[tid + s]);
        __syncthreads();
    }
    mx = red[0];
    __syncthreads();

    float sum = 0.f;
    #pragma unroll
    for (int t = 0; t < 8; ++t) {
        v[t] = expf(v[t] - mx);
        sum += v[t];
    }
    red[tid] = sum;
    __syncthreads();
    for (int s = 128; s > 0; s >>= 1) {
        if (tid < s) red[tid] += red[tid + s];
        __syncthreads();
    }
    sum = red[0];

    float inv = 1.f / sum;
    #pragma unroll
    for (int t = 0; t < 8; ++t)
        row[tid + t * 256] = v[t] * inv;
}

// O[h,b] = S[b,h] @ V_h  (2048 x 512, K = 2048).  Note (h,b) pair order in O
// reproduces the reference's transpose(1,0,2,3)+reshape exactly.
__global__ void k_pv() {
    int p = blockIdx.z;
    int b = p >> 3, h = p & 7;
    const float* Sp = g_S + (long long)p * SQv * SKv;
    const float* Vh = g_v + (long long)b * SKv * VPv + h * DVv;
    float* Op = g_O + ((long long)(h * Bv + b)) * SQv * DVv;
    gemm_tile_nn(Sp, SKv, Vh, VPv, Op, DVv, nullptr, SKv);
}

// out = O @ W_o + b_o  (16384 x 4096 @ 4096 x 512)
__global__ void k_out(const float* __restrict__ Wo, const float* __restrict__ bo,
                      float* __restrict__ out) {
    gemm_tile_nn(g_O, VPv, Wo, Dv, out, Dv, bo, VPv);
}

// ---------------------------------------------------------------------------
// Launch
// ---------------------------------------------------------------------------
extern "C" void kernel_launch(void* const* d_in, const int* in_sizes, int n_in,
                              void* d_out, int out_size) {
    const float* q_in = (const float*)d_in[0];
    const float* k_in = (const float*)d_in[1];
    const float* v_in = (const float*)d_in[2];
    const float* W_q  = (const float*)d_in[3];
    const float* W_k  = (const float*)d_in[4];
    const float* W_v  = (const float*)d_in[5];
    const float* W_o  = (const float*)d_in[6];
    const float* b_o  = (const float*)d_in[7];
    const int*   mask = (const int*)d_in[8];
    float* out = (float*)d_out;

    const int MROWS = Bv * SQv;  // 16384

    dim3 blk(NTHREADS);

    // Projections
    k_proj_q<<<dim3(QPv / BN, MROWS / BM), blk>>>(q_in, W_q);
    k_proj_k<<<dim3(QPv / BN, MROWS / BM), blk>>>(k_in, W_k);
    k_proj_v<<<dim3(VPv / BN, MROWS / BM), blk>>>(v_in, W_v);

    // Attention scores
    k_qk<<<dim3(SKv / BN, SQv / BM, Bv * Hv), blk>>>();

    // Masked + scaled softmax (in place on S)
    k_softmax_m<<<dim3(SQv, Bv * Hv), blk>>>(mask);

    // PV
    k_pv<<<dim3(DVv / BN, SQv / BM, Bv * Hv), blk>>>();

    // Output projection + bias
    k_out<<<dim3(Dv / BN, MROWS / BM), blk>>>(W_o, b_o, out);
}

// round 3
// speedup vs baseline: 1.0006x; 1.0006x over previous
#include <cuda_runtime.h>

// Problem constants
#define Bv   8
#define SQv  2048
#define SKv  2048
#define Dv   512
#define Hv   8
#define QPv  512
#define VPv  4096
#define DQv  64     // QP / H
#define DVv  512    // VP / H

// GEMM tiling
#define BM 128
#define BN 128
#define BKK 8
#define TM 8
#define TN 8
#define NTHREADS 256

// Scratch (static device allocations — allowed; runtime alloc is not)
__device__ float g_q[(size_t)Bv * SQv * QPv];            // 33.5 MB
__device__ float g_k[(size_t)Bv * SKv * QPv];            // 33.5 MB
__device__ float g_v[(size_t)Bv * SKv * VPv];            // 268 MB
__device__ float g_S[(size_t)Bv * Hv * SQv * SKv];       // 1.07 GB
__device__ float g_O[(size_t)Hv * Bv * SQv * DVv];       // 268 MB  layout [h][b][s][d]

// ---------------------------------------------------------------------------
// Core tile GEMM: C[BMxBN] += A[BMxK] * B[KxBN]   (A,B,C row-major w/ strides)
// 256 threads, each computes an 8x8 microtile. All dims assumed multiples of
// tile sizes (true for this problem: 16384/2048 x 512/2048/4096, K % 8 == 0).
// ---------------------------------------------------------------------------
__device__ __forceinline__ void gemm_tile_nn(
    const float* __restrict__ A, int lda,
    const float* __restrict__ Bm, int ldb,
    float* __restrict__ C, int ldc,
    const float* __restrict__ bias,
    int K)
{
    __shared__ float As[BKK][BM];
    __shared__ float Bs[BKK][BN];

    const int tid  = threadIdx.x;
    const int m0   = blockIdx.y * BM;
    const int n0   = blockIdx.x * BN;
    const int tr   = tid >> 4;          // 0..15
    const int tc   = tid & 15;          // 0..15
    const int arow = tid >> 1;          // 0..127
    const int acol = (tid & 1) * 4;     // 0 or 4
    const int brow = tid >> 5;          // 0..7
    const int bcol = (tid & 31) * 4;    // 0..124

    float acc[TM][TN];
    #pragma unroll
    for (int i = 0; i < TM; ++i)
        #pragma unroll
        for (int j = 0; j < TN; ++j) acc[i][j] = 0.f;

    for (int k0 = 0; k0 < K; k0 += BKK) {
        float4 av = *(const float4*)&A[(long long)(m0 + arow) * lda + k0 + acol];
        As[acol + 0][arow] = av.x;
        As[acol + 1][arow] = av.y;
        As[acol + 2][arow] = av.z;
        As[acol + 3][arow] = av.w;
        float4 bv = *(const float4*)&Bm[(long long)(k0 + brow) * ldb + n0 + bcol];
        *(float4*)&Bs[brow][bcol] = bv;
        __syncthreads();

        #pragma unroll
        for (int k = 0; k < BKK; ++k) {
            float a[TM], b[TN];
            *(float4*)&a[0] = *(const float4*)&As[k][tr * TM];
            *(float4*)&a[4] = *(const float4*)&As[k][tr * TM + 4];
            *(float4*)&b[0] = *(const float4*)&Bs[k][tc * TN];
            *(float4*)&b[4] = *(const float4*)&Bs[k][tc * TN + 4];
            #pragma unroll
            for (int i = 0; i < TM; ++i)
                #pragma unroll
                for (int j = 0; j < TN; ++j)
                    acc[i][j] = fmaf(a[i], b[j], acc[i][j]);
        }
        __syncthreads();
    }

    #pragma unroll
    for (int i = 0; i < TM; ++i) {
        long long m = m0 + tr * TM + i;
        #pragma unroll
        for (int j = 0; j < TN; j += 4) {
            int n = n0 + tc * TN + j;
            float4 o;
            o.x = acc[i][j + 0] + (bias ? bias[n + 0] : 0.f);
            o.y = acc[i][j + 1] + (bias ? bias[n + 1] : 0.f);
            o.z = acc[i][j + 2] + (bias ? bias[n + 2] : 0.f);
            o.w = acc[i][j + 3] + (bias ? bias[n + 3] : 0.f);
            *(float4*)&C[m * ldc + n] = o;
        }
    }
}

// NT variant: C = A * B^T, with B stored N x K row-major (stride ldb)
__device__ __forceinline__ void gemm_tile_nt(
    const float* __restrict__ A, int lda,
    const float* __restrict__ Bt, int ldb,
    float* __restrict__ C, int ldc,
    int K)
{
    __shared__ float As[BKK][BM];
    __shared__ float Bs[BKK][BN];

    const int tid  = threadIdx.x;
    const int m0   = blockIdx.y * BM;
    const int n0   = blockIdx.x * BN;
    const int tr   = tid >> 4;
    const int tc   = tid & 15;
    const int arow = tid >> 1;          // 0..127
    const int acol = (tid & 1) * 4;     // 0 or 4

    float acc[TM][TN];
    #pragma unroll
    for (int i = 0; i < TM; ++i)
        #pragma unroll
        for (int j = 0; j < TN; ++j) acc[i][j] = 0.f;

    for (int k0 = 0; k0 < K; k0 += BKK) {
        float4 av = *(const float4*)&A[(long long)(m0 + arow) * lda + k0 + acol];
        As[acol + 0][arow] = av.x;
        As[acol + 1][arow] = av.y;
        As[acol + 2][arow] = av.z;
        As[acol + 3][arow] = av.w;
        float4 bv = *(const float4*)&Bt[(long long)(n0 + arow) * ldb + k0 + acol];
        Bs[acol + 0][arow] = bv.x;
        Bs[acol + 1][arow] = bv.y;
        Bs[acol + 2][arow] = bv.z;
        Bs[acol + 3][arow] = bv.w;
        __syncthreads();

        #pragma unroll
        for (int k = 0; k < BKK; ++k) {
            float a[TM], b[TN];
            *(float4*)&a[0] = *(const float4*)&As[k][tr * TM];
            *(float4*)&a[4] = *(const float4*)&As[k][tr * TM + 4];
            *(float4*)&b[0] = *(const float4*)&Bs[k][tc * TN];
            *(float4*)&b[4] = *(const float4*)&Bs[k][tc * TN + 4];
            #pragma unroll
            for (int i = 0; i < TM; ++i)
                #pragma unroll
                for (int j = 0; j < TN; ++j)
                    acc[i][j] = fmaf(a[i], b[j], acc[i][j]);
        }
        __syncthreads();
    }

    #pragma unroll
    for (int i = 0; i < TM; ++i) {
        long long m = m0 + tr * TM + i;
        #pragma unroll
        for (int j = 0; j < TN; j += 4) {
            int n = n0 + tc * TN + j;
            *(float4*)&C[m * ldc + n] = *(float4*)&acc[i][j];
        }
    }
}

// ---------------------------------------------------------------------------
// Kernels
// ---------------------------------------------------------------------------

// q = q_in @ W_q  (16384 x 512 @ 512 x 512)
__global__ void k_proj_q(const float* __restrict__ X, const float* __restrict__ W) {
    gemm_tile_nn(X, Dv, W, QPv, g_q, QPv, nullptr, Dv);
}
// k = k_in @ W_k
__global__ void k_proj_k(const float* __restrict__ X, const float* __restrict__ W) {
    gemm_tile_nn(X, Dv, W, QPv, g_k, QPv, nullptr, Dv);
}
// v = v_in @ W_v  (16384 x 4096)
__global__ void k_proj_v(const float* __restrict__ X, const float* __restrict__ W) {
    gemm_tile_nn(X, Dv, W, VPv, g_v, VPv, nullptr, Dv);
}

// S[b,h] = Q_h @ K_h^T   (2048 x 2048, K = 64), grid.z = b*H + h
__global__ void k_qk() {
    int p = blockIdx.z;
    int b = p >> 3, h = p & 7;
    const float* Qh = g_q + (long long)b * SQv * QPv + h * DQv;
    const float* Kh = g_k + (long long)b * SKv * QPv + h * DQv;
    float* Sp = g_S + (long long)p * SQv * SKv;
    gemm_tile_nt(Qh, QPv, Kh, QPv, Sp, SKv, DQv);
}

// In-place masked softmax over rows of S. grid = (SQ, B*H), 256 threads.
__global__ void k_softmax() {
    const int p = blockIdx.y;
    const int b = p >> 3;
    const int i = blockIdx.x;
    float* row = g_S + ((long long)p * SQv + i) * SKv;
    const int tid = threadIdx.x;

    // mask pointer comes from a device-visible copy set up by kernel args;
    // we read it via the global pointer stored below.
    extern __shared__ float sred[];   // 256 floats
    const int* mrow = ((const int* const*)0 == 0) ? nullptr : nullptr; // placeholder (unused)
    (void)mrow;

    // mask is passed through constant kernel parameter instead:
    // (see k_softmax_m below)
    (void)row; (void)b; (void)tid; (void)sred;
}

// Real softmax kernel (takes mask pointer as parameter)
__global__ void k_softmax_m(const int* __restrict__ mask) {
    const int p = blockIdx.y;          // b*H + h
    const int b = p >> 3;
    const int i = blockIdx.x;
    float* __restrict__ row = g_S + ((long long)p * SQv + i) * SKv;
    const int* __restrict__ mrow = mask + ((long long)b * SQv + i) * SKv;
    const int tid = threadIdx.x;       // 256 threads, 8 elems each

    __shared__ float red[256];

    float v[8];
    float mx = -3.402823466e+38f;
    #pragma unroll
    for (int t = 0; t < 8; ++t) {
        int j = tid + t * 256;
        float x = row[j];
        if (mrow[j] == 0) x = -1e9f;
        x *= 0.125f;                   // / sqrt(512/8) = /8
        v[t] = x;
        mx = fmaxf(mx, x);
    }
    red[tid] = mx;
    __syncthreads();
    for (int s = 128; s > 0; s >>= 1) {
        if (tid < s) red[tid] = fmaxf(red[tid], red[tid + s]);
        __syncthreads();
    }
    mx = red[0];
    __syncthreads();

    float sum = 0.f;
    #pragma unroll
    for (int t = 0; t < 8; ++t) {
        v[t] = expf(v[t] - mx);
        sum += v[t];
    }
    red[tid] = sum;
    __syncthreads();
    for (int s = 128; s > 0; s >>= 1) {
        if (tid < s) red[tid] += red[tid + s];
        __syncthreads();
    }
    sum = red[0];

    float inv = 1.f / sum;
    #pragma unroll
    for (int t = 0; t < 8; ++t)
        row[tid + t * 256] = v[t] * inv;
}

// O[h,b] = S[b,h] @ V_h  (2048 x 512, K = 2048).  Note (h,b) pair order in O
// reproduces the reference's transpose(1,0,2,3)+reshape exactly.
__global__ void k_pv() {
    int p = blockIdx.z;
    int b = p >> 3, h = p & 7;
    const float* Sp = g_S + (long long)p * SQv * SKv;
    const float* Vh = g_v + (long long)b * SKv * VPv + h * DVv;
    float* Op = g_O + ((long long)(h * Bv + b)) * SQv * DVv;
    gemm_tile_nn(Sp, SKv, Vh, VPv, Op, DVv, nullptr, SKv);
}

// out = O @ W_o + b_o  (16384 x 4096 @ 4096 x 512)
__global__ void k_out(const float* __restrict__ Wo, const float* __restrict__ bo,
                      float* __restrict__ out) {
    gemm_tile_nn(g_O, VPv, Wo, Dv, out, Dv, bo, VPv);
}

// ---------------------------------------------------------------------------
// Launch
// ---------------------------------------------------------------------------
extern "C" void kernel_launch(void* const* d_in, const int* in_sizes, int n_in,
                              void* d_out, int out_size) {
    const float* q_in = (const float*)d_in[0];
    const float* k_in = (const float*)d_in[1];
    const float* v_in = (const float*)d_in[2];
    const float* W_q  = (const float*)d_in[3];
    const float* W_k  = (const float*)d_in[4];
    const float* W_v  = (const float*)d_in[5];
    const float* W_o  = (const float*)d_in[6];
    const float* b_o  = (const float*)d_in[7];
    const int*   mask = (const int*)d_in[8];
    float* out = (float*)d_out;

    const int MROWS = Bv * SQv;  // 16384

    dim3 blk(NTHREADS);

    // Projections
    k_proj_q<<<dim3(QPv / BN, MROWS / BM), blk>>>(q_in, W_q);
    k_proj_k<<<dim3(QPv / BN, MROWS / BM), blk>>>(k_in, W_k);
    k_proj_v<<<dim3(VPv / BN, MROWS / BM), blk>>>(v_in, W_v);

    // Attention scores
    k_qk<<<dim3(SKv / BN, SQv / BM, Bv * Hv), blk>>>();

    // Masked + scaled softmax (in place on S)
    k_softmax_m<<<dim3(SQv, Bv * Hv), blk>>>(mask);

    // PV
    k_pv<<<dim3(DVv / BN, SQv / BM, Bv * Hv), blk>>>();

    // Output projection + bias
    k_out<<<dim3(Dv / BN, MROWS / BM), blk>>>(W_o, b_o, out);
}